// round 1
// baseline (speedup 1.0000x reference)
#include <cuda_runtime.h>

#define SDIM 256
#define TQ   64
#define KS   16
#define AST  17            // A-tile row stride (64 x 16 tile)
#define BST  260           // B-tile row stride (16 x 256 tile, float4-aligned)
#define PST  257           // P/O smem row stride (conflict-free transpose)

// 64 MB scratch for projected V (allowed: __device__ global array)
__device__ float g_V[(size_t)SDIM * SDIM * SDIM];

// ---------------------------------------------------------------------------
// Kernel A: V[b] = value[b] @ v_weight[b] + v_bias   (per-batch 256x256x256)
// grid (4, 256), block 256. Each thread: 4 rows x 16 cols (4x float4 blocks).
// ---------------------------------------------------------------------------
__global__ void __launch_bounds__(256, 2)
vproj_kernel(const float* __restrict__ val,
             const float* __restrict__ w,
             const float* __restrict__ bias)
{
    __shared__ float As[TQ * AST];
    __shared__ float Bs[KS * BST];

    const int b   = blockIdx.y;
    const int r0  = blockIdx.x * TQ;
    const int tid = threadIdx.x;
    const int tx  = tid & 15;
    const int ty  = tid >> 4;

    const float* A = val + (size_t)b * SDIM * SDIM;
    const float* W = w   + (size_t)b * SDIM * SDIM;

    float4 acc[4][4];
#pragma unroll
    for (int r = 0; r < 4; ++r)
#pragma unroll
        for (int i = 0; i < 4; ++i) acc[r][i] = make_float4(0.f, 0.f, 0.f, 0.f);

    for (int k0 = 0; k0 < SDIM; k0 += KS) {
#pragma unroll
        for (int rr = 0; rr < 4; ++rr) {
            int row = rr * 16 + ty;
            As[row * AST + tx] = A[(size_t)(r0 + row) * SDIM + k0 + tx];
        }
#pragma unroll
        for (int v = 0; v < 4; ++v) {
            int idx = tid + v * 256;            // float4 index within 16x256 tile
            int r   = idx >> 6;
            int c4  = (idx & 63) << 2;
            *(float4*)&Bs[r * BST + c4] =
                *(const float4*)&W[(size_t)(k0 + r) * SDIM + c4];
        }
        __syncthreads();
#pragma unroll
        for (int kk = 0; kk < KS; ++kk) {
            float a[4];
            float4 bv[4];
#pragma unroll
            for (int r = 0; r < 4; ++r) a[r] = As[(ty * 4 + r) * AST + kk];
#pragma unroll
            for (int i = 0; i < 4; ++i)
                bv[i] = *(const float4*)&Bs[kk * BST + tx * 4 + 64 * i];
#pragma unroll
            for (int r = 0; r < 4; ++r)
#pragma unroll
                for (int i = 0; i < 4; ++i) {
                    acc[r][i].x = fmaf(a[r], bv[i].x, acc[r][i].x);
                    acc[r][i].y = fmaf(a[r], bv[i].y, acc[r][i].y);
                    acc[r][i].z = fmaf(a[r], bv[i].z, acc[r][i].z);
                    acc[r][i].w = fmaf(a[r], bv[i].w, acc[r][i].w);
                }
        }
        __syncthreads();
    }

    // bias + store
#pragma unroll
    for (int r = 0; r < 4; ++r) {
        int row = r0 + ty * 4 + r;
#pragma unroll
        for (int i = 0; i < 4; ++i) {
            int c = tx * 4 + 64 * i;
            float4 bb = *(const float4*)&bias[(size_t)row * SDIM + c];
            float4 o  = acc[r][i];
            o.x += bb.x; o.y += bb.y; o.z += bb.z; o.w += bb.w;
            *(float4*)&g_V[(size_t)b * SDIM * SDIM + (size_t)row * SDIM + c] = o;
        }
    }
}

// ---------------------------------------------------------------------------
// Kernel B: per (64-query tile, batch):
//   S = Q K^T / 16  -> softmax rows -> dropout -> P -> O = P V -> out[b,d,q]
// grid (4, 256), block 256, dynamic smem (P 64x257 | A 64x17 | B 16x260)
// ---------------------------------------------------------------------------
__global__ void __launch_bounds__(256, 2)
attn_kernel(const float* __restrict__ q,
            const float* __restrict__ k,
            const float* __restrict__ du,
            float* __restrict__ out)
{
    extern __shared__ float sm[];
    float* Ps = sm;                       // TQ * PST
    float* As = Ps + TQ * PST;            // TQ * AST
    float* Bs = As + TQ * AST;            // KS * BST

    const int b   = blockIdx.y;
    const int q0  = blockIdx.x * TQ;
    const int tid = threadIdx.x;
    const int tx  = tid & 15;
    const int ty  = tid >> 4;

    const float* Q = q + (size_t)b * SDIM * SDIM;
    const float* K = k + (size_t)b * SDIM * SDIM;

    float4 acc[4][4];
#pragma unroll
    for (int r = 0; r < 4; ++r)
#pragma unroll
        for (int i = 0; i < 4; ++i) acc[r][i] = make_float4(0.f, 0.f, 0.f, 0.f);

    // ---- Phase 1: S = Q K^T ------------------------------------------------
    for (int d0 = 0; d0 < SDIM; d0 += KS) {
#pragma unroll
        for (int rr = 0; rr < 4; ++rr) {
            int row = rr * 16 + ty;
            As[row * AST + tx] = Q[(size_t)(q0 + row) * SDIM + d0 + tx];
        }
        // Bs[c][kcol] = K[kcol][d0+c]  (transpose on store)
#pragma unroll
        for (int kb = 0; kb < 16; ++kb) {
            int kcol = kb * 16 + ty;
            Bs[tx * BST + kcol] = K[(size_t)kcol * SDIM + d0 + tx];
        }
        __syncthreads();
#pragma unroll
        for (int kk = 0; kk < KS; ++kk) {
            float a[4];
            float4 bv[4];
#pragma unroll
            for (int r = 0; r < 4; ++r) a[r] = As[(ty * 4 + r) * AST + kk];
#pragma unroll
            for (int i = 0; i < 4; ++i)
                bv[i] = *(const float4*)&Bs[kk * BST + tx * 4 + 64 * i];
#pragma unroll
            for (int r = 0; r < 4; ++r)
#pragma unroll
                for (int i = 0; i < 4; ++i) {
                    acc[r][i].x = fmaf(a[r], bv[i].x, acc[r][i].x);
                    acc[r][i].y = fmaf(a[r], bv[i].y, acc[r][i].y);
                    acc[r][i].z = fmaf(a[r], bv[i].z, acc[r][i].z);
                    acc[r][i].w = fmaf(a[r], bv[i].w, acc[r][i].w);
                }
        }
        __syncthreads();
    }

    // ---- Softmax over keys (each row split across 16 lanes of a half-warp).
    // Note: qk_bias is constant along the key axis -> softmax-invariant -> skipped.
    const float scale = 0.0625f;   // 1/sqrt(256)
    float rinv[4];
#pragma unroll
    for (int r = 0; r < 4; ++r) {
        float m = -1e30f;
#pragma unroll
        for (int i = 0; i < 4; ++i) {
            acc[r][i].x *= scale; acc[r][i].y *= scale;
            acc[r][i].z *= scale; acc[r][i].w *= scale;
            m = fmaxf(m, fmaxf(fmaxf(acc[r][i].x, acc[r][i].y),
                               fmaxf(acc[r][i].z, acc[r][i].w)));
        }
#pragma unroll
        for (int o = 8; o; o >>= 1)
            m = fmaxf(m, __shfl_xor_sync(0xffffffffu, m, o));
        float s = 0.f;
#pragma unroll
        for (int i = 0; i < 4; ++i) {
            acc[r][i].x = __expf(acc[r][i].x - m);
            acc[r][i].y = __expf(acc[r][i].y - m);
            acc[r][i].z = __expf(acc[r][i].z - m);
            acc[r][i].w = __expf(acc[r][i].w - m);
            s += acc[r][i].x + acc[r][i].y + acc[r][i].z + acc[r][i].w;
        }
#pragma unroll
        for (int o = 8; o; o >>= 1)
            s += __shfl_xor_sync(0xffffffffu, s, o);
        rinv[r] = 1.0f / (0.9f * s);   // folds the 1/(1-p) dropout rescale
    }

    // ---- Dropout + write P to smem -----------------------------------------
#pragma unroll
    for (int r = 0; r < 4; ++r) {
        int qq = ty * 4 + r;
        const float* Du = du + (size_t)b * SDIM * SDIM + (size_t)(q0 + qq) * SDIM;
#pragma unroll
        for (int i = 0; i < 4; ++i) {
            int c = tx * 4 + 64 * i;
            float4 u = *(const float4*)&Du[c];
            float* pr = &Ps[qq * PST + c];
            pr[0] = (u.x >= 0.1f) ? acc[r][i].x * rinv[r] : 0.f;
            pr[1] = (u.y >= 0.1f) ? acc[r][i].y * rinv[r] : 0.f;
            pr[2] = (u.z >= 0.1f) ? acc[r][i].z * rinv[r] : 0.f;
            pr[3] = (u.w >= 0.1f) ? acc[r][i].w * rinv[r] : 0.f;
        }
    }
    __syncthreads();

    // ---- Phase 2: O = P @ V -------------------------------------------------
#pragma unroll
    for (int r = 0; r < 4; ++r)
#pragma unroll
        for (int i = 0; i < 4; ++i) acc[r][i] = make_float4(0.f, 0.f, 0.f, 0.f);

    const float* Vb = g_V + (size_t)b * SDIM * SDIM;
    for (int k0 = 0; k0 < SDIM; k0 += KS) {
#pragma unroll
        for (int v = 0; v < 4; ++v) {
            int idx = tid + v * 256;
            int r   = idx >> 6;
            int c4  = (idx & 63) << 2;
            *(float4*)&Bs[r * BST + c4] =
                *(const float4*)&Vb[(size_t)(k0 + r) * SDIM + c4];
        }
        __syncthreads();
#pragma unroll
        for (int kk = 0; kk < KS; ++kk) {
            float p[4];
            float4 bv[4];
#pragma unroll
            for (int r = 0; r < 4; ++r) p[r] = Ps[(ty * 4 + r) * PST + k0 + kk];
#pragma unroll
            for (int i = 0; i < 4; ++i)
                bv[i] = *(const float4*)&Bs[kk * BST + tx * 4 + 64 * i];
#pragma unroll
            for (int r = 0; r < 4; ++r)
#pragma unroll
                for (int i = 0; i < 4; ++i) {
                    acc[r][i].x = fmaf(p[r], bv[i].x, acc[r][i].x);
                    acc[r][i].y = fmaf(p[r], bv[i].y, acc[r][i].y);
                    acc[r][i].z = fmaf(p[r], bv[i].z, acc[r][i].z);
                    acc[r][i].w = fmaf(p[r], bv[i].w, acc[r][i].w);
                }
        }
        __syncthreads();
    }

    // ---- Stage O in smem (reuse Ps), then coalesced transposed store -------
#pragma unroll
    for (int r = 0; r < 4; ++r) {
        int qq = ty * 4 + r;
#pragma unroll
        for (int i = 0; i < 4; ++i) {
            int c = tx * 4 + 64 * i;
            float* pr = &Ps[qq * PST + c];
            pr[0] = acc[r][i].x; pr[1] = acc[r][i].y;
            pr[2] = acc[r][i].z; pr[3] = acc[r][i].w;
        }
    }
    __syncthreads();

    // out[b, d, q0+qq] = O[qq, d]
    {
        int qq = tid & 63;
        int dd = tid >> 6;           // 0..3
        float* Ob = out + (size_t)b * SDIM * SDIM;
#pragma unroll 8
        for (int jj = 0; jj < 64; ++jj) {
            int d = jj * 4 + dd;
            Ob[(size_t)d * SDIM + q0 + qq] = Ps[qq * PST + d];
        }
    }
}

// ---------------------------------------------------------------------------
extern "C" void kernel_launch(void* const* d_in, const int* in_sizes, int n_in,
                              void* d_out, int out_size)
{
    const float* query = (const float*)d_in[0];
    const float* key   = (const float*)d_in[1];
    const float* value = (const float*)d_in[2];
    const float* dropu = (const float*)d_in[3];
    // d_in[4] = qk_bias: constant along softmax axis -> provably dead, skipped
    const float* vw    = (const float*)d_in[5];
    const float* vb    = (const float*)d_in[6];
    float* out = (float*)d_out;

    dim3 grid(SDIM / TQ, SDIM);
    dim3 blk(256);

    size_t shm = (size_t)(TQ * PST + TQ * AST + KS * BST) * sizeof(float);
    cudaFuncSetAttribute(attn_kernel,
                         cudaFuncAttributeMaxDynamicSharedMemorySize, (int)shm);

    vproj_kernel<<<grid, blk>>>(value, vw, vb);
    attn_kernel<<<grid, blk, shm>>>(query, key, dropu, out);
}

// round 2
// speedup vs baseline: 1.9486x; 1.9486x over previous
#include <cuda_runtime.h>

#define SDIM 256

// 64 MB scratch for projected V (allowed: __device__ global array)
__device__ float g_V[(size_t)SDIM * SDIM * SDIM];

// ---------------------------------------------------------------------------
// tf32 helpers
// ---------------------------------------------------------------------------
__device__ __forceinline__ unsigned f2tf(float x) {
    unsigned r;
    asm("cvt.rna.tf32.f32 %0, %1;" : "=r"(r) : "f"(x));
    return r;
}

__device__ __forceinline__ void mma8(float* c,
                                     unsigned a0, unsigned a1, unsigned a2, unsigned a3,
                                     unsigned b0, unsigned b1) {
    asm volatile(
        "mma.sync.aligned.m16n8k8.row.col.f32.tf32.tf32.f32 "
        "{%0,%1,%2,%3}, {%4,%5,%6,%7}, {%8,%9}, {%0,%1,%2,%3};\n"
        : "+f"(c[0]), "+f"(c[1]), "+f"(c[2]), "+f"(c[3])
        : "r"(a0), "r"(a1), "r"(a2), "r"(a3), "r"(b0), "r"(b1));
}

// Smem strides (words). A-operand strides ≡ 4 (mod 32), B-operand ≡ 8 (mod 32)
// -> conflict-free fragment loads.
#define AST 20     // A tiles: 128 x 16 (Q tile / value tile)
#define BST 264    // B tiles: 16 x 256 (W / K^T / V tiles)
#define PST 260    // P tile: 128 x 256 (A-operand of phase 2)
#define OST 132    // O transpose stage: 256 x 128

// attn dynamic smem layout (in 32-bit words)
#define PS_WORDS  33792                  // max(128*260, 256*132)
#define VS_OFF    PS_WORDS               // 16*264 = 4224
#define RED_OFF   (VS_OFF + 16 * BST)    // 128*4 floats
#define RED2_OFF  (RED_OFF + 512)
#define SMEM_WORDS (RED2_OFF + 512)      // 39040 words = 156160 B

// ---------------------------------------------------------------------------
// Kernel A: g_V[b] = value[b] @ v_weight[b] + v_bias   (tf32 tensor cores)
// grid (2, 256), block 512. CTA tile 128x256, warp tile 32x64 (4x4 warps).
// ---------------------------------------------------------------------------
__global__ void __launch_bounds__(512, 1)
vproj_kernel(const float* __restrict__ val,
             const float* __restrict__ w,
             const float* __restrict__ bias)
{
    __shared__ unsigned As[128 * AST];
    __shared__ unsigned Bs[16 * BST];

    const int b   = blockIdx.y;
    const int m0  = blockIdx.x * 128;
    const int tid = threadIdx.x;
    const int lane = tid & 31, wid = tid >> 5;
    const int wm = wid >> 2, wn = wid & 3;
    const int g = lane >> 2, tg = lane & 3;

    const float* A = val + (size_t)b * SDIM * SDIM;
    const float* W = w   + (size_t)b * SDIM * SDIM;

    float c[2][8][4];
#pragma unroll
    for (int mt = 0; mt < 2; ++mt)
#pragma unroll
        for (int nt = 0; nt < 8; ++nt)
#pragma unroll
            for (int i = 0; i < 4; ++i) c[mt][nt][i] = 0.f;

    const int ar = tid >> 2, ac = (tid & 3) << 2;   // A stage: 1 float4
    const int br = tid >> 6, bc = (tid & 63) << 2;  // B stage: 2 float4 (rows br, br+8)

    float4 fa  = *(const float4*)&A[(size_t)(m0 + ar) * SDIM + ac];
    float4 fb0 = *(const float4*)&W[(size_t)br * SDIM + bc];
    float4 fb1 = *(const float4*)&W[(size_t)(br + 8) * SDIM + bc];

    for (int cc = 0; cc < 16; ++cc) {
        {
            unsigned* p = &As[ar * AST + ac];
            p[0] = f2tf(fa.x); p[1] = f2tf(fa.y); p[2] = f2tf(fa.z); p[3] = f2tf(fa.w);
            p = &Bs[br * BST + bc];
            p[0] = f2tf(fb0.x); p[1] = f2tf(fb0.y); p[2] = f2tf(fb0.z); p[3] = f2tf(fb0.w);
            p = &Bs[(br + 8) * BST + bc];
            p[0] = f2tf(fb1.x); p[1] = f2tf(fb1.y); p[2] = f2tf(fb1.z); p[3] = f2tf(fb1.w);
        }
        __syncthreads();
        if (cc < 15) {
            int k0 = (cc + 1) * 16;
            fa  = *(const float4*)&A[(size_t)(m0 + ar) * SDIM + k0 + ac];
            fb0 = *(const float4*)&W[(size_t)(k0 + br) * SDIM + bc];
            fb1 = *(const float4*)&W[(size_t)(k0 + br + 8) * SDIM + bc];
        }
#pragma unroll
        for (int ks = 0; ks < 16; ks += 8) {
            unsigned a[2][4];
#pragma unroll
            for (int mt = 0; mt < 2; ++mt) {
                int r0 = (wm * 32 + mt * 16 + g) * AST + ks + tg;
                a[mt][0] = As[r0];
                a[mt][2] = As[r0 + 4];
                a[mt][1] = As[r0 + 8 * AST];
                a[mt][3] = As[r0 + 8 * AST + 4];
            }
#pragma unroll
            for (int nt = 0; nt < 8; ++nt) {
                int cb = (ks + tg) * BST + wn * 64 + nt * 8 + g;
                unsigned b0 = Bs[cb];
                unsigned b1 = Bs[cb + 4 * BST];
                mma8(c[0][nt], a[0][0], a[0][1], a[0][2], a[0][3], b0, b1);
                mma8(c[1][nt], a[1][0], a[1][1], a[1][2], a[1][3], b0, b1);
            }
        }
        __syncthreads();
    }

    float* gv = g_V + (size_t)b * SDIM * SDIM;
#pragma unroll
    for (int mt = 0; mt < 2; ++mt)
#pragma unroll
        for (int h = 0; h < 2; ++h) {
            int row = m0 + wm * 32 + mt * 16 + h * 8 + g;
#pragma unroll
            for (int nt = 0; nt < 8; ++nt) {
                int col = wn * 64 + nt * 8 + tg * 2;
                float2 bb = *(const float2*)&bias[(size_t)row * SDIM + col];
                float2 o;
                o.x = c[mt][nt][h * 2]     + bb.x;
                o.y = c[mt][nt][h * 2 + 1] + bb.y;
                *(float2*)&gv[(size_t)row * SDIM + col] = o;
            }
        }
}

// ---------------------------------------------------------------------------
// Kernel B: attention. CTA = 128 queries x 256 keys (one batch).
//   S = QK^T/16 (tensor) -> softmax (cross-warp smem reduce) -> dropout ->
//   P (tf32 smem) -> O = P V (tensor) -> transposed store out[b,d,q].
// grid (2, 256), block 512, dynamic smem 156160 B.
// ---------------------------------------------------------------------------
__global__ void __launch_bounds__(512, 1)
attn_kernel(const float* __restrict__ q,
            const float* __restrict__ k,
            const float* __restrict__ du,
            float* __restrict__ out)
{
    extern __shared__ float smf[];
    unsigned* smu = (unsigned*)smf;

    const int b   = blockIdx.y;
    const int q0  = blockIdx.x * 128;
    const int tid = threadIdx.x;
    const int lane = tid & 31, wid = tid >> 5;
    const int wm = wid >> 2, wn = wid & 3;
    const int g = lane >> 2, tg = lane & 3;

    unsigned* Qs = smu;             // 128*20 (phase 1 only, inside P region)
    unsigned* Ks = smu + 2560;      // 16*264 (phase 1 only, inside P region)
    unsigned* Ps = smu;             // 128*260
    unsigned* Vs = smu + VS_OFF;    // 16*264
    float* redA  = smf + RED_OFF;   // 128*4
    float* redB  = smf + RED2_OFF;  // 128*4
    float* Os    = smf;             // 256*132 (epilogue, reuses P region)

    const float* Q = q + (size_t)b * SDIM * SDIM;
    const float* K = k + (size_t)b * SDIM * SDIM;

    float c[2][8][4];
#pragma unroll
    for (int mt = 0; mt < 2; ++mt)
#pragma unroll
        for (int nt = 0; nt < 8; ++nt)
#pragma unroll
            for (int i = 0; i < 4; ++i) c[mt][nt][i] = 0.f;

    // ---- Phase 1: S = Q K^T ------------------------------------------------
    const int ar = tid >> 2, ac = (tid & 3) << 2;   // Q stage
    const int kk = tid & 255, dd = (tid >> 8) * 8;  // K stage (transposed)

    float4 fq  = *(const float4*)&Q[(size_t)(q0 + ar) * SDIM + ac];
    float4 fk0 = *(const float4*)&K[(size_t)kk * SDIM + dd];
    float4 fk1 = *(const float4*)&K[(size_t)kk * SDIM + dd + 4];

    for (int cc = 0; cc < 16; ++cc) {
        {
            unsigned* p = &Qs[ar * AST + ac];
            p[0] = f2tf(fq.x); p[1] = f2tf(fq.y); p[2] = f2tf(fq.z); p[3] = f2tf(fq.w);
            Ks[(dd + 0) * BST + kk] = f2tf(fk0.x);
            Ks[(dd + 1) * BST + kk] = f2tf(fk0.y);
            Ks[(dd + 2) * BST + kk] = f2tf(fk0.z);
            Ks[(dd + 3) * BST + kk] = f2tf(fk0.w);
            Ks[(dd + 4) * BST + kk] = f2tf(fk1.x);
            Ks[(dd + 5) * BST + kk] = f2tf(fk1.y);
            Ks[(dd + 6) * BST + kk] = f2tf(fk1.z);
            Ks[(dd + 7) * BST + kk] = f2tf(fk1.w);
        }
        __syncthreads();
        if (cc < 15) {
            int d0 = (cc + 1) * 16;
            fq  = *(const float4*)&Q[(size_t)(q0 + ar) * SDIM + d0 + ac];
            fk0 = *(const float4*)&K[(size_t)kk * SDIM + d0 + dd];
            fk1 = *(const float4*)&K[(size_t)kk * SDIM + d0 + dd + 4];
        }
#pragma unroll
        for (int ks = 0; ks < 16; ks += 8) {
            unsigned a[2][4];
#pragma unroll
            for (int mt = 0; mt < 2; ++mt) {
                int r0 = (wm * 32 + mt * 16 + g) * AST + ks + tg;
                a[mt][0] = Qs[r0];
                a[mt][2] = Qs[r0 + 4];
                a[mt][1] = Qs[r0 + 8 * AST];
                a[mt][3] = Qs[r0 + 8 * AST + 4];
            }
#pragma unroll
            for (int nt = 0; nt < 8; ++nt) {
                int cb = (ks + tg) * BST + wn * 64 + nt * 8 + g;
                unsigned b0 = Ks[cb];
                unsigned b1 = Ks[cb + 4 * BST];
                mma8(c[0][nt], a[0][0], a[0][1], a[0][2], a[0][3], b0, b1);
                mma8(c[1][nt], a[1][0], a[1][1], a[1][2], a[1][3], b0, b1);
            }
        }
        __syncthreads();
    }

    // ---- Softmax (qk_bias is softmax-invariant along keys -> skipped) -------
    const float scale = 0.0625f;  // 1/sqrt(256)
#pragma unroll
    for (int mt = 0; mt < 2; ++mt)
#pragma unroll
        for (int h = 0; h < 2; ++h) {
            float m = -1e30f;
#pragma unroll
            for (int nt = 0; nt < 8; ++nt) {
                c[mt][nt][h * 2]     *= scale;
                c[mt][nt][h * 2 + 1] *= scale;
                m = fmaxf(m, fmaxf(c[mt][nt][h * 2], c[mt][nt][h * 2 + 1]));
            }
            m = fmaxf(m, __shfl_xor_sync(0xffffffffu, m, 1));
            m = fmaxf(m, __shfl_xor_sync(0xffffffffu, m, 2));
            int row = wm * 32 + mt * 16 + h * 8 + g;
            if (tg == 0) redA[row * 4 + wn] = m;
        }
    __syncthreads();

#pragma unroll
    for (int mt = 0; mt < 2; ++mt)
#pragma unroll
        for (int h = 0; h < 2; ++h) {
            int row = wm * 32 + mt * 16 + h * 8 + g;
            float m = fmaxf(fmaxf(redA[row * 4 + 0], redA[row * 4 + 1]),
                            fmaxf(redA[row * 4 + 2], redA[row * 4 + 3]));
            float s = 0.f;
#pragma unroll
            for (int nt = 0; nt < 8; ++nt) {
                float e0 = __expf(c[mt][nt][h * 2]     - m);
                float e1 = __expf(c[mt][nt][h * 2 + 1] - m);
                c[mt][nt][h * 2]     = e0;
                c[mt][nt][h * 2 + 1] = e1;
                s += e0 + e1;
            }
            s += __shfl_xor_sync(0xffffffffu, s, 1);
            s += __shfl_xor_sync(0xffffffffu, s, 2);
            if (tg == 0) redB[row * 4 + wn] = s;
        }
    __syncthreads();

    float rinv[2][2];
#pragma unroll
    for (int mt = 0; mt < 2; ++mt)
#pragma unroll
        for (int h = 0; h < 2; ++h) {
            int row = wm * 32 + mt * 16 + h * 8 + g;
            float s = redB[row * 4 + 0] + redB[row * 4 + 1] +
                      redB[row * 4 + 2] + redB[row * 4 + 3];
            rinv[mt][h] = 1.0f / (0.9f * s);  // folds 1/(1-p) dropout rescale
        }

    // ---- Dropout + store P (tf32) to smem -----------------------------------
    const float* DU = du + (size_t)b * SDIM * SDIM;
#pragma unroll
    for (int mt = 0; mt < 2; ++mt)
#pragma unroll
        for (int h = 0; h < 2; ++h) {
            int row = wm * 32 + mt * 16 + h * 8 + g;
#pragma unroll
            for (int nt = 0; nt < 8; ++nt) {
                int col = wn * 64 + nt * 8 + tg * 2;
                float2 u = *(const float2*)&DU[(size_t)(q0 + row) * SDIM + col];
                float p0 = (u.x >= 0.1f) ? c[mt][nt][h * 2]     * rinv[mt][h] : 0.f;
                float p1 = (u.y >= 0.1f) ? c[mt][nt][h * 2 + 1] * rinv[mt][h] : 0.f;
                uint2 pv; pv.x = f2tf(p0); pv.y = f2tf(p1);
                *(uint2*)&Ps[row * PST + col] = pv;
            }
        }
    __syncthreads();

    // ---- Phase 2: O = P @ V --------------------------------------------------
#pragma unroll
    for (int mt = 0; mt < 2; ++mt)
#pragma unroll
        for (int nt = 0; nt < 8; ++nt)
#pragma unroll
            for (int i = 0; i < 4; ++i) c[mt][nt][i] = 0.f;

    const float* GV = g_V + (size_t)b * SDIM * SDIM;
    const int vr = tid >> 6, vc = (tid & 63) << 2;
    float4 fv0 = *(const float4*)&GV[(size_t)vr * SDIM + vc];
    float4 fv1 = *(const float4*)&GV[(size_t)(vr + 8) * SDIM + vc];

    for (int cc = 0; cc < 16; ++cc) {
        {
            unsigned* p = &Vs[vr * BST + vc];
            p[0] = f2tf(fv0.x); p[1] = f2tf(fv0.y); p[2] = f2tf(fv0.z); p[3] = f2tf(fv0.w);
            p = &Vs[(vr + 8) * BST + vc];
            p[0] = f2tf(fv1.x); p[1] = f2tf(fv1.y); p[2] = f2tf(fv1.z); p[3] = f2tf(fv1.w);
        }
        __syncthreads();
        if (cc < 15) {
            int k0 = (cc + 1) * 16;
            fv0 = *(const float4*)&GV[(size_t)(k0 + vr) * SDIM + vc];
            fv1 = *(const float4*)&GV[(size_t)(k0 + vr + 8) * SDIM + vc];
        }
        int kbase = cc * 16;
#pragma unroll
        for (int ks = 0; ks < 16; ks += 8) {
            unsigned a[2][4];
#pragma unroll
            for (int mt = 0; mt < 2; ++mt) {
                int r0 = (wm * 32 + mt * 16 + g) * PST + kbase + ks + tg;
                a[mt][0] = Ps[r0];
                a[mt][2] = Ps[r0 + 4];
                a[mt][1] = Ps[r0 + 8 * PST];
                a[mt][3] = Ps[r0 + 8 * PST + 4];
            }
#pragma unroll
            for (int nt = 0; nt < 8; ++nt) {
                int cb = (ks + tg) * BST + wn * 64 + nt * 8 + g;
                unsigned b0 = Vs[cb];
                unsigned b1 = Vs[cb + 4 * BST];
                mma8(c[0][nt], a[0][0], a[0][1], a[0][2], a[0][3], b0, b1);
                mma8(c[1][nt], a[1][0], a[1][1], a[1][2], a[1][3], b0, b1);
            }
        }
        __syncthreads();
    }

    // ---- Epilogue: stage O transposed [d][q], coalesced store ---------------
#pragma unroll
    for (int mt = 0; mt < 2; ++mt)
#pragma unroll
        for (int h = 0; h < 2; ++h) {
            int row = wm * 32 + mt * 16 + h * 8 + g;
#pragma unroll
            for (int nt = 0; nt < 8; ++nt) {
                int col = wn * 64 + nt * 8 + tg * 2;
                Os[col * OST + row]       = c[mt][nt][h * 2];
                Os[(col + 1) * OST + row] = c[mt][nt][h * 2 + 1];
            }
        }
    __syncthreads();

    float* Ob = out + (size_t)b * SDIM * SDIM;
#pragma unroll
    for (int j = 0; j < 16; ++j) {
        int idx = tid + j * 512;
        int d = idx >> 5, qv = (idx & 31) << 2;
        *(float4*)&Ob[(size_t)d * SDIM + q0 + qv] = *(float4*)&Os[d * OST + qv];
    }
}

// ---------------------------------------------------------------------------
extern "C" void kernel_launch(void* const* d_in, const int* in_sizes, int n_in,
                              void* d_out, int out_size)
{
    const float* query = (const float*)d_in[0];
    const float* key   = (const float*)d_in[1];
    const float* value = (const float*)d_in[2];
    const float* dropu = (const float*)d_in[3];
    // d_in[4] = qk_bias: constant along softmax axis -> provably dead, skipped
    const float* vw    = (const float*)d_in[5];
    const float* vb    = (const float*)d_in[6];
    float* out = (float*)d_out;

    size_t shm = (size_t)SMEM_WORDS * sizeof(float);
    cudaFuncSetAttribute(attn_kernel,
                         cudaFuncAttributeMaxDynamicSharedMemorySize, (int)shm);

    dim3 grid(2, SDIM);
    vproj_kernel<<<grid, 512>>>(value, vw, vb);
    attn_kernel<<<grid, 512, shm>>>(query, key, dropu, out);
}

// round 3
// speedup vs baseline: 1.9840x; 1.0182x over previous
#include <cuda_runtime.h>

#define SDIM 256

// 64 MB scratch for projected V, stored as tf32 bit patterns
__device__ unsigned g_V[(size_t)SDIM * SDIM * SDIM];

// ---------------------------------------------------------------------------
__device__ __forceinline__ unsigned f2tf(float x) {
    unsigned r;
    asm("cvt.rna.tf32.f32 %0, %1;" : "=r"(r) : "f"(x));
    return r;
}

__device__ __forceinline__ void mma8(float* c,
                                     unsigned a0, unsigned a1, unsigned a2, unsigned a3,
                                     unsigned b0, unsigned b1) {
    asm volatile(
        "mma.sync.aligned.m16n8k8.row.col.f32.tf32.tf32.f32 "
        "{%0,%1,%2,%3}, {%4,%5,%6,%7}, {%8,%9}, {%0,%1,%2,%3};\n"
        : "+f"(c[0]), "+f"(c[1]), "+f"(c[2]), "+f"(c[3])
        : "r"(a0), "r"(a1), "r"(a2), "r"(a3), "r"(b0), "r"(b1));
}

// Strides (words). Bank-conflict-free fragment access:
//  A-frag addr = AST*g + tg  (20g+tg unique mod 32)
//  B-frag addr = BST*tg + g  (8tg+g unique mod 32)
//  P-frag addr = PST*g + tg  (4g+tg unique mod 32)
#define AST 20     // A tiles: 64 x 16
#define BST 264    // B tiles: 16 x 256
#define PST 260    // P tile:  64 x 256
#define OST 68     // O transpose stage: 256 x 64 (4c+r unique mod 32)

// attn dynamic smem layout (words). Double-buffered Q/K live inside P region.
#define QS0_OFF   0
#define QS1_OFF   1280
#define KS0_OFF   2560
#define KS1_OFF   6784           // 2560 + 16*264
#define VS0_OFF   16640          // = 64*PST (after P region)
#define VS1_OFF   (VS0_OFF + 16 * BST)
#define RED_OFF   (VS1_OFF + 16 * BST)       // 25088
#define RED2_OFF  (RED_OFF + 256)
#define SMEM_WORDS (RED2_OFF + 256)          // 25600 words = 102400 B

// ---------------------------------------------------------------------------
// Kernel A: g_V[b] = tf32(value[b] @ v_weight[b] + v_bias)
// grid (4, 256), block 256 (8 warps, 2x4), CTA tile 64x256, warp tile 32x64.
// Double-buffered smem, 1 barrier per k-chunk.
// ---------------------------------------------------------------------------
__global__ void __launch_bounds__(256, 2)
vproj_kernel(const float* __restrict__ val,
             const float* __restrict__ w,
             const float* __restrict__ bias)
{
    __shared__ unsigned As[2][64 * AST];
    __shared__ unsigned Bs[2][16 * BST];

    const int b   = blockIdx.y;
    const int m0  = blockIdx.x * 64;
    const int tid = threadIdx.x;
    const int lane = tid & 31, wid = tid >> 5;
    const int wm = wid >> 2, wn = wid & 3;
    const int g = lane >> 2, tg = lane & 3;

    const float* A = val + (size_t)b * SDIM * SDIM;
    const float* W = w   + (size_t)b * SDIM * SDIM;

    float c[2][8][4];
#pragma unroll
    for (int mt = 0; mt < 2; ++mt)
#pragma unroll
        for (int nt = 0; nt < 8; ++nt)
#pragma unroll
            for (int i = 0; i < 4; ++i) c[mt][nt][i] = 0.f;

    const int ar = tid >> 2, ac = (tid & 3) << 2;   // A: 1 float4
    const int vr = tid >> 6, vc = (tid & 63) << 2;  // B: 4 float4 (rows vr+4j)

    float4 fa, fb[4];
    // load chunk 0
    fa = *(const float4*)&A[(size_t)(m0 + ar) * SDIM + ac];
#pragma unroll
    for (int j = 0; j < 4; ++j)
        fb[j] = *(const float4*)&W[(size_t)(vr + 4 * j) * SDIM + vc];
    // put chunk 0 -> buf 0
    {
        unsigned* p = &As[0][ar * AST + ac];
        p[0] = f2tf(fa.x); p[1] = f2tf(fa.y); p[2] = f2tf(fa.z); p[3] = f2tf(fa.w);
#pragma unroll
        for (int j = 0; j < 4; ++j) {
            uint4 t; t.x = f2tf(fb[j].x); t.y = f2tf(fb[j].y);
            t.z = f2tf(fb[j].z); t.w = f2tf(fb[j].w);
            *(uint4*)&Bs[0][(vr + 4 * j) * BST + vc] = t;
        }
    }
    // load chunk 1
    fa = *(const float4*)&A[(size_t)(m0 + ar) * SDIM + 16 + ac];
#pragma unroll
    for (int j = 0; j < 4; ++j)
        fb[j] = *(const float4*)&W[(size_t)(16 + vr + 4 * j) * SDIM + vc];
    __syncthreads();

#pragma unroll 2
    for (int cc = 0; cc < 16; ++cc) {
        const int cur = cc & 1;
        if (cc < 15) {
            unsigned* p = &As[cur ^ 1][ar * AST + ac];
            p[0] = f2tf(fa.x); p[1] = f2tf(fa.y); p[2] = f2tf(fa.z); p[3] = f2tf(fa.w);
#pragma unroll
            for (int j = 0; j < 4; ++j) {
                uint4 t; t.x = f2tf(fb[j].x); t.y = f2tf(fb[j].y);
                t.z = f2tf(fb[j].z); t.w = f2tf(fb[j].w);
                *(uint4*)&Bs[cur ^ 1][(vr + 4 * j) * BST + vc] = t;
            }
        }
        if (cc < 14) {
            int k0 = (cc + 2) * 16;
            fa = *(const float4*)&A[(size_t)(m0 + ar) * SDIM + k0 + ac];
#pragma unroll
            for (int j = 0; j < 4; ++j)
                fb[j] = *(const float4*)&W[(size_t)(k0 + vr + 4 * j) * SDIM + vc];
        }
#pragma unroll
        for (int ks = 0; ks < 16; ks += 8) {
            unsigned a[2][4];
#pragma unroll
            for (int mt = 0; mt < 2; ++mt) {
                int r0 = (wm * 32 + mt * 16 + g) * AST + ks + tg;
                a[mt][0] = As[cur][r0];
                a[mt][2] = As[cur][r0 + 4];
                a[mt][1] = As[cur][r0 + 8 * AST];
                a[mt][3] = As[cur][r0 + 8 * AST + 4];
            }
#pragma unroll
            for (int nt = 0; nt < 8; ++nt) {
                int cb = (ks + tg) * BST + wn * 64 + nt * 8 + g;
                unsigned b0 = Bs[cur][cb];
                unsigned b1 = Bs[cur][cb + 4 * BST];
                mma8(c[0][nt], a[0][0], a[0][1], a[0][2], a[0][3], b0, b1);
                mma8(c[1][nt], a[1][0], a[1][1], a[1][2], a[1][3], b0, b1);
            }
        }
        if (cc < 15) __syncthreads();
    }

    unsigned* gv = g_V + (size_t)b * SDIM * SDIM;
#pragma unroll
    for (int mt = 0; mt < 2; ++mt)
#pragma unroll
        for (int h = 0; h < 2; ++h) {
            int row = m0 + wm * 32 + mt * 16 + h * 8 + g;
#pragma unroll
            for (int nt = 0; nt < 8; ++nt) {
                int col = wn * 64 + nt * 8 + tg * 2;
                float2 bb = *(const float2*)&bias[(size_t)row * SDIM + col];
                uint2 o;
                o.x = f2tf(c[mt][nt][h * 2]     + bb.x);
                o.y = f2tf(c[mt][nt][h * 2 + 1] + bb.y);
                *(uint2*)&gv[(size_t)row * SDIM + col] = o;
            }
        }
}

// ---------------------------------------------------------------------------
// Kernel B: attention. CTA = 64 queries x 256 keys of one batch.
// grid (4, 256), block 256 (8 warps, 2x4), dynamic smem 102400 B, 2 CTAs/SM.
// ---------------------------------------------------------------------------
__global__ void __launch_bounds__(256, 2)
attn_kernel(const float* __restrict__ q,
            const float* __restrict__ k,
            const float* __restrict__ du,
            float* __restrict__ out)
{
    extern __shared__ float smf[];
    unsigned* smu = (unsigned*)smf;

    const int b   = blockIdx.y;
    const int q0  = blockIdx.x * 64;
    const int tid = threadIdx.x;
    const int lane = tid & 31, wid = tid >> 5;
    const int wm = wid >> 2, wn = wid & 3;
    const int g = lane >> 2, tg = lane & 3;

    unsigned* Qs[2] = { smu + QS0_OFF, smu + QS1_OFF };
    unsigned* Ks[2] = { smu + KS0_OFF, smu + KS1_OFF };
    unsigned* Vs[2] = { smu + VS0_OFF, smu + VS1_OFF };
    unsigned* Ps = smu;             // 64*260 (after phase 1)
    float* redA  = smf + RED_OFF;   // 64*4
    float* redB  = smf + RED2_OFF;  // 64*4
    float* Os    = smf;             // 256*68 (epilogue)

    const float* Q = q + (size_t)b * SDIM * SDIM;
    const float* K = k + (size_t)b * SDIM * SDIM;

    float c[2][8][4];
#pragma unroll
    for (int mt = 0; mt < 2; ++mt)
#pragma unroll
        for (int nt = 0; nt < 8; ++nt)
#pragma unroll
            for (int i = 0; i < 4; ++i) c[mt][nt][i] = 0.f;

    // ---- Phase 1: S = Q K^T (double-buffered) -------------------------------
    const int ar = tid >> 2, ac = (tid & 3) << 2;   // Q stage: 1 float4
    const int kk = tid;                              // K stage: row kk, 16 d

    float4 fq, fk[4];
    fq = *(const float4*)&Q[(size_t)(q0 + ar) * SDIM + ac];
#pragma unroll
    for (int j = 0; j < 4; ++j)
        fk[j] = *(const float4*)&K[(size_t)kk * SDIM + j * 4];
    {
        unsigned* p = &Qs[0][ar * AST + ac];
        p[0] = f2tf(fq.x); p[1] = f2tf(fq.y); p[2] = f2tf(fq.z); p[3] = f2tf(fq.w);
#pragma unroll
        for (int j = 0; j < 4; ++j) {
            Ks[0][(j * 4 + 0) * BST + kk] = f2tf(fk[j].x);
            Ks[0][(j * 4 + 1) * BST + kk] = f2tf(fk[j].y);
            Ks[0][(j * 4 + 2) * BST + kk] = f2tf(fk[j].z);
            Ks[0][(j * 4 + 3) * BST + kk] = f2tf(fk[j].w);
        }
    }
    fq = *(const float4*)&Q[(size_t)(q0 + ar) * SDIM + 16 + ac];
#pragma unroll
    for (int j = 0; j < 4; ++j)
        fk[j] = *(const float4*)&K[(size_t)kk * SDIM + 16 + j * 4];
    __syncthreads();

#pragma unroll 2
    for (int cc = 0; cc < 16; ++cc) {
        const int cur = cc & 1;
        if (cc < 15) {
            unsigned* p = &Qs[cur ^ 1][ar * AST + ac];
            p[0] = f2tf(fq.x); p[1] = f2tf(fq.y); p[2] = f2tf(fq.z); p[3] = f2tf(fq.w);
            unsigned* Kb = Ks[cur ^ 1];
#pragma unroll
            for (int j = 0; j < 4; ++j) {
                Kb[(j * 4 + 0) * BST + kk] = f2tf(fk[j].x);
                Kb[(j * 4 + 1) * BST + kk] = f2tf(fk[j].y);
                Kb[(j * 4 + 2) * BST + kk] = f2tf(fk[j].z);
                Kb[(j * 4 + 3) * BST + kk] = f2tf(fk[j].w);
            }
        }
        if (cc < 14) {
            int d0 = (cc + 2) * 16;
            fq = *(const float4*)&Q[(size_t)(q0 + ar) * SDIM + d0 + ac];
#pragma unroll
            for (int j = 0; j < 4; ++j)
                fk[j] = *(const float4*)&K[(size_t)kk * SDIM + d0 + j * 4];
        }
#pragma unroll
        for (int ks = 0; ks < 16; ks += 8) {
            unsigned a[2][4];
#pragma unroll
            for (int mt = 0; mt < 2; ++mt) {
                int r0 = (wm * 32 + mt * 16 + g) * AST + ks + tg;
                a[mt][0] = Qs[cur][r0];
                a[mt][2] = Qs[cur][r0 + 4];
                a[mt][1] = Qs[cur][r0 + 8 * AST];
                a[mt][3] = Qs[cur][r0 + 8 * AST + 4];
            }
#pragma unroll
            for (int nt = 0; nt < 8; ++nt) {
                int cb = (ks + tg) * BST + wn * 64 + nt * 8 + g;
                unsigned b0 = Ks[cur][cb];
                unsigned b1 = Ks[cur][cb + 4 * BST];
                mma8(c[0][nt], a[0][0], a[0][1], a[0][2], a[0][3], b0, b1);
                mma8(c[1][nt], a[1][0], a[1][1], a[1][2], a[1][3], b0, b1);
            }
        }
        __syncthreads();   // also fences Q/K region before P overwrites it
    }

    // ---- Softmax (qk_bias is softmax-invariant along keys -> skipped) -------
    const float scale = 0.0625f;  // 1/sqrt(256)
#pragma unroll
    for (int mt = 0; mt < 2; ++mt)
#pragma unroll
        for (int h = 0; h < 2; ++h) {
            float m = -1e30f;
#pragma unroll
            for (int nt = 0; nt < 8; ++nt) {
                c[mt][nt][h * 2]     *= scale;
                c[mt][nt][h * 2 + 1] *= scale;
                m = fmaxf(m, fmaxf(c[mt][nt][h * 2], c[mt][nt][h * 2 + 1]));
            }
            m = fmaxf(m, __shfl_xor_sync(0xffffffffu, m, 1));
            m = fmaxf(m, __shfl_xor_sync(0xffffffffu, m, 2));
            int row = wm * 32 + mt * 16 + h * 8 + g;
            if (tg == 0) redA[row * 4 + wn] = m;
        }
    __syncthreads();

#pragma unroll
    for (int mt = 0; mt < 2; ++mt)
#pragma unroll
        for (int h = 0; h < 2; ++h) {
            int row = wm * 32 + mt * 16 + h * 8 + g;
            float m = fmaxf(fmaxf(redA[row * 4 + 0], redA[row * 4 + 1]),
                            fmaxf(redA[row * 4 + 2], redA[row * 4 + 3]));
            float s = 0.f;
#pragma unroll
            for (int nt = 0; nt < 8; ++nt) {
                float e0 = __expf(c[mt][nt][h * 2]     - m);
                float e1 = __expf(c[mt][nt][h * 2 + 1] - m);
                c[mt][nt][h * 2]     = e0;
                c[mt][nt][h * 2 + 1] = e1;
                s += e0 + e1;
            }
            s += __shfl_xor_sync(0xffffffffu, s, 1);
            s += __shfl_xor_sync(0xffffffffu, s, 2);
            if (tg == 0) redB[row * 4 + wn] = s;
        }
    __syncthreads();

    float rinv[2][2];
#pragma unroll
    for (int mt = 0; mt < 2; ++mt)
#pragma unroll
        for (int h = 0; h < 2; ++h) {
            int row = wm * 32 + mt * 16 + h * 8 + g;
            float s = redB[row * 4 + 0] + redB[row * 4 + 1] +
                      redB[row * 4 + 2] + redB[row * 4 + 3];
            rinv[mt][h] = 1.0f / (0.9f * s);  // folds 1/(1-p) dropout rescale
        }

    // ---- Dropout + store P (tf32) to smem -----------------------------------
    const float* DU = du + (size_t)b * SDIM * SDIM;
#pragma unroll
    for (int mt = 0; mt < 2; ++mt)
#pragma unroll
        for (int h = 0; h < 2; ++h) {
            int row = wm * 32 + mt * 16 + h * 8 + g;
#pragma unroll
            for (int nt = 0; nt < 8; ++nt) {
                int col = wn * 64 + nt * 8 + tg * 2;
                float2 u = *(const float2*)&DU[(size_t)(q0 + row) * SDIM + col];
                float p0 = (u.x >= 0.1f) ? c[mt][nt][h * 2]     * rinv[mt][h] : 0.f;
                float p1 = (u.y >= 0.1f) ? c[mt][nt][h * 2 + 1] * rinv[mt][h] : 0.f;
                uint2 pv; pv.x = f2tf(p0); pv.y = f2tf(p1);
                *(uint2*)&Ps[row * PST + col] = pv;
            }
        }
    __syncthreads();

    // ---- Phase 2: O = P @ V (V already tf32 in g_V; double-buffered) --------
#pragma unroll
    for (int mt = 0; mt < 2; ++mt)
#pragma unroll
        for (int nt = 0; nt < 8; ++nt)
#pragma unroll
            for (int i = 0; i < 4; ++i) c[mt][nt][i] = 0.f;

    const unsigned* GV = g_V + (size_t)b * SDIM * SDIM;
    const int vr = tid >> 6, vc = (tid & 63) << 2;
    uint4 fv[4];
#pragma unroll
    for (int j = 0; j < 4; ++j)
        fv[j] = *(const uint4*)&GV[(size_t)(vr + 4 * j) * SDIM + vc];
#pragma unroll
    for (int j = 0; j < 4; ++j)
        *(uint4*)&Vs[0][(vr + 4 * j) * BST + vc] = fv[j];
#pragma unroll
    for (int j = 0; j < 4; ++j)
        fv[j] = *(const uint4*)&GV[(size_t)(16 + vr + 4 * j) * SDIM + vc];
    __syncthreads();

#pragma unroll 2
    for (int cc = 0; cc < 16; ++cc) {
        const int cur = cc & 1;
        if (cc < 15) {
#pragma unroll
            for (int j = 0; j < 4; ++j)
                *(uint4*)&Vs[cur ^ 1][(vr + 4 * j) * BST + vc] = fv[j];
        }
        if (cc < 14) {
            int k0 = (cc + 2) * 16;
#pragma unroll
            for (int j = 0; j < 4; ++j)
                fv[j] = *(const uint4*)&GV[(size_t)(k0 + vr + 4 * j) * SDIM + vc];
        }
        int kbase = cc * 16;
#pragma unroll
        for (int ks = 0; ks < 16; ks += 8) {
            unsigned a[2][4];
#pragma unroll
            for (int mt = 0; mt < 2; ++mt) {
                int r0 = (wm * 32 + mt * 16 + g) * PST + kbase + ks + tg;
                a[mt][0] = Ps[r0];
                a[mt][2] = Ps[r0 + 4];
                a[mt][1] = Ps[r0 + 8 * PST];
                a[mt][3] = Ps[r0 + 8 * PST + 4];
            }
#pragma unroll
            for (int nt = 0; nt < 8; ++nt) {
                int cb = (ks + tg) * BST + wn * 64 + nt * 8 + g;
                unsigned b0 = Vs[cur][cb];
                unsigned b1 = Vs[cur][cb + 4 * BST];
                mma8(c[0][nt], a[0][0], a[0][1], a[0][2], a[0][3], b0, b1);
                mma8(c[1][nt], a[1][0], a[1][1], a[1][2], a[1][3], b0, b1);
            }
        }
        if (cc < 15) __syncthreads();
    }
    __syncthreads();   // P region dead; safe to overwrite with Os

    // ---- Epilogue: stage O transposed [d][q], coalesced store ---------------
#pragma unroll
    for (int mt = 0; mt < 2; ++mt)
#pragma unroll
        for (int h = 0; h < 2; ++h) {
            int row = wm * 32 + mt * 16 + h * 8 + g;
#pragma unroll
            for (int nt = 0; nt < 8; ++nt) {
                int col = wn * 64 + nt * 8 + tg * 2;
                Os[col * OST + row]       = c[mt][nt][h * 2];
                Os[(col + 1) * OST + row] = c[mt][nt][h * 2 + 1];
            }
        }
    __syncthreads();

    float* Ob = out + (size_t)b * SDIM * SDIM;
#pragma unroll
    for (int j = 0; j < 16; ++j) {
        int idx = tid + j * 256;
        int d = idx >> 4, qv = (idx & 15) << 2;
        *(float4*)&Ob[(size_t)d * SDIM + q0 + qv] = *(float4*)&Os[d * OST + qv];
    }
}

// ---------------------------------------------------------------------------
extern "C" void kernel_launch(void* const* d_in, const int* in_sizes, int n_in,
                              void* d_out, int out_size)
{
    const float* query = (const float*)d_in[0];
    const float* key   = (const float*)d_in[1];
    const float* value = (const float*)d_in[2];
    const float* dropu = (const float*)d_in[3];
    // d_in[4] = qk_bias: constant along softmax axis -> provably dead, skipped
    const float* vw    = (const float*)d_in[5];
    const float* vb    = (const float*)d_in[6];
    float* out = (float*)d_out;

    size_t shm = (size_t)SMEM_WORDS * sizeof(float);
    cudaFuncSetAttribute(attn_kernel,
                         cudaFuncAttributeMaxDynamicSharedMemorySize, (int)shm);

    dim3 grid(4, SDIM);
    vproj_kernel<<<grid, 256>>>(value, vw, vb);
    attn_kernel<<<grid, 256, shm>>>(query, key, dropu, out);
}

// round 4
// speedup vs baseline: 2.4131x; 1.2163x over previous
#include <cuda_runtime.h>

#define SDIM 256

// 64 MB scratch for projected V, stored as tf32 bit patterns
__device__ unsigned g_V[(size_t)SDIM * SDIM * SDIM];

// ---------------------------------------------------------------------------
__device__ __forceinline__ unsigned f2tf(float x) {
    unsigned r;
    asm("cvt.rna.tf32.f32 %0, %1;" : "=r"(r) : "f"(x));
    return r;
}

__device__ __forceinline__ void mma8(float* c,
                                     unsigned a0, unsigned a1, unsigned a2, unsigned a3,
                                     unsigned b0, unsigned b1) {
    asm volatile(
        "mma.sync.aligned.m16n8k8.row.col.f32.tf32.tf32.f32 "
        "{%0,%1,%2,%3}, {%4,%5,%6,%7}, {%8,%9}, {%0,%1,%2,%3};\n"
        : "+f"(c[0]), "+f"(c[1]), "+f"(c[2]), "+f"(c[3])
        : "r"(a0), "r"(a1), "r"(a2), "r"(a3), "r"(b0), "r"(b1));
}

__device__ __forceinline__ void cpa16(unsigned dst, const void* src) {
    asm volatile("cp.async.cg.shared.global [%0], [%1], 16;\n"
                 :: "r"(dst), "l"(src));
}
#define CP_COMMIT()  asm volatile("cp.async.commit_group;\n")
#define CP_WAIT(N)   asm volatile("cp.async.wait_group %0;\n" :: "n"(N))

// Strides (words), all fragment patterns conflict-free mod 32:
//  [row][d] stride 20:  A-frag (20g+tg), K/B-frag natural (20g+tg)
//  [k][n]  stride 264:  B-frag (8tg+g)
//  P stride 260:        P-frag (4g+tg)
//  O stage stride 68:   store (8tg+g)
#define QST 20
#define KST 20
#define VST 264
#define PST 260
#define OST 68

// attn smem layout (words)
#define S1SZ      (64 * QST + 256 * KST)        // 6400 per phase-1 stage (x3 = 19200)
#define P_WORDS   (64 * PST)                    // 16640
#define V_OFF     P_WORDS
#define VSTG      (16 * VST)                    // 4224 per phase-2 stage (x2)
#define RED_OFF   (V_OFF + 2 * VSTG)            // 25088
#define RED2_OFF  (RED_OFF + 256)
#define SMEM_WORDS (RED2_OFF + 256)             // 25600 words = 102400 B
// phase-1 stages live at [0, 19200) overlapping P and V0 regions (dead then);
// epilogue O stage (256*68=17408) also overlaps P (dead then).

// ---------------------------------------------------------------------------
// Kernel A: g_V[b] = tf32(value[b] @ v_weight[b] + v_bias)
// grid (4,256), block 256 (2x4 warps, 32x64 warp tiles), 3-stage cp.async.
// ---------------------------------------------------------------------------
#define VP_STG (64 * QST + 16 * VST)   // 1280 + 4224 = 5504 words per stage

__global__ void __launch_bounds__(256, 2)
vproj_kernel(const float* __restrict__ val,
             const float* __restrict__ w,
             const float* __restrict__ bias)
{
    extern __shared__ float smf[];
    const unsigned sb = (unsigned)__cvta_generic_to_shared(smf);

    const int b   = blockIdx.y;
    const int m0  = blockIdx.x * 64;
    const int tid = threadIdx.x;
    const int lane = tid & 31, wid = tid >> 5;
    const int wm = wid >> 2, wn = wid & 3;
    const int g = lane >> 2, tg = lane & 3;

    const float* A = val + (size_t)b * SDIM * SDIM;
    const float* W = w   + (size_t)b * SDIM * SDIM;

    const int ar = tid >> 2, ac = (tid & 3) << 2;
    const int br = tid >> 6, bc = (tid & 63) << 2;

    // issue stage s (k0 = s*16) into buffer s%3
    auto issue = [&](int s) {
        const int k0 = s * 16;
        const unsigned ba = sb + (unsigned)((s % 3) * VP_STG) * 4u;
        cpa16(ba + (unsigned)(ar * QST + ac) * 4u, A + (size_t)(m0 + ar) * SDIM + k0 + ac);
        const unsigned bb = ba + 64u * QST * 4u;
#pragma unroll
        for (int j = 0; j < 4; ++j)
            cpa16(bb + (unsigned)((br + 4 * j) * VST + bc) * 4u,
                  W + (size_t)(k0 + br + 4 * j) * SDIM + bc);
    };

    float c[2][8][4];
#pragma unroll
    for (int mt = 0; mt < 2; ++mt)
#pragma unroll
        for (int nt = 0; nt < 8; ++nt)
#pragma unroll
            for (int i = 0; i < 4; ++i) c[mt][nt][i] = 0.f;

    issue(0); CP_COMMIT();
    issue(1); CP_COMMIT();

#pragma unroll 1
    for (int cc = 0; cc < 16; ++cc) {
        CP_WAIT(1);
        __syncthreads();
        if (cc < 14) issue(cc + 2);
        CP_COMMIT();

        const float* As = smf + (cc % 3) * VP_STG;
        const float* Bs = As + 64 * QST;
#pragma unroll
        for (int ks = 0; ks < 16; ks += 8) {
            unsigned a[2][4];
#pragma unroll
            for (int mt = 0; mt < 2; ++mt) {
                const float* p = As + (wm * 32 + mt * 16 + g) * QST + ks + tg;
                a[mt][0] = f2tf(p[0]);
                a[mt][2] = f2tf(p[4]);
                a[mt][1] = f2tf(p[8 * QST]);
                a[mt][3] = f2tf(p[8 * QST + 4]);
            }
#pragma unroll
            for (int nt = 0; nt < 8; ++nt) {
                const float* p = Bs + (ks + tg) * VST + wn * 64 + nt * 8 + g;
                unsigned b0 = f2tf(p[0]);
                unsigned b1 = f2tf(p[4 * VST]);
                mma8(c[0][nt], a[0][0], a[0][1], a[0][2], a[0][3], b0, b1);
                mma8(c[1][nt], a[1][0], a[1][1], a[1][2], a[1][3], b0, b1);
            }
        }
    }

    unsigned* gv = g_V + (size_t)b * SDIM * SDIM;
#pragma unroll
    for (int mt = 0; mt < 2; ++mt)
#pragma unroll
        for (int h = 0; h < 2; ++h) {
            int row = m0 + wm * 32 + mt * 16 + h * 8 + g;
#pragma unroll
            for (int nt = 0; nt < 8; ++nt) {
                int col = wn * 64 + nt * 8 + tg * 2;
                float2 bb2 = *(const float2*)&bias[(size_t)row * SDIM + col];
                uint2 o;
                o.x = f2tf(c[mt][nt][h * 2]     + bb2.x);
                o.y = f2tf(c[mt][nt][h * 2 + 1] + bb2.y);
                *(uint2*)&gv[(size_t)row * SDIM + col] = o;
            }
        }
}

// ---------------------------------------------------------------------------
// Kernel B: attention. CTA = 64 queries x 256 keys of one batch.
// grid (4,256), block 256, dynamic smem 102400 B, 2 CTAs/SM.
// ---------------------------------------------------------------------------
__global__ void __launch_bounds__(256, 2)
attn_kernel(const float* __restrict__ q,
            const float* __restrict__ k,
            const float* __restrict__ du,
            float* __restrict__ out)
{
    extern __shared__ float smf[];
    unsigned* smu = (unsigned*)smf;
    const unsigned sb = (unsigned)__cvta_generic_to_shared(smf);

    const int b   = blockIdx.y;
    const int q0  = blockIdx.x * 64;
    const int tid = threadIdx.x;
    const int lane = tid & 31, wid = tid >> 5;
    const int wm = wid >> 2, wn = wid & 3;
    const int g = lane >> 2, tg = lane & 3;

    unsigned* Ps = smu;             // 64*260 (written after phase 1)
    float* redA  = smf + RED_OFF;
    float* redB  = smf + RED2_OFF;
    float* Os    = smf;             // 256*68 (epilogue)

    const float* Q = q + (size_t)b * SDIM * SDIM;
    const float* K = k + (size_t)b * SDIM * SDIM;
    const unsigned* GV = g_V + (size_t)b * SDIM * SDIM;

    const int ar = tid >> 2, ac = (tid & 3) << 2;

    // phase-1 stage s (d0 = s*16) -> buffer s%3 at word offset (s%3)*S1SZ
    auto issue1 = [&](int s) {
        const int d0 = s * 16;
        const unsigned bq = sb + (unsigned)((s % 3) * S1SZ) * 4u;
        cpa16(bq + (unsigned)(ar * QST + ac) * 4u, Q + (size_t)(q0 + ar) * SDIM + d0 + ac);
        const unsigned bk = bq + 64u * QST * 4u;
#pragma unroll
        for (int j = 0; j < 4; ++j)
            cpa16(bk + (unsigned)(tid * KST + j * 4) * 4u,
                  K + (size_t)tid * SDIM + d0 + j * 4);
    };
    // phase-2 V stage s (k0 = s*16) -> buffer s%2
    auto issue2 = [&](int s) {
        const int k0 = s * 16;
        const unsigned bv = sb + (unsigned)(V_OFF + (s % 2) * VSTG) * 4u;
#pragma unroll
        for (int t = 0; t < 4; ++t) {
            int idx = tid + t * 256;
            int row = idx >> 6, c4 = (idx & 63) << 2;
            cpa16(bv + (unsigned)(row * VST + c4) * 4u,
                  GV + (size_t)(k0 + row) * SDIM + c4);
        }
    };

    float c[2][8][4];
#pragma unroll
    for (int mt = 0; mt < 2; ++mt)
#pragma unroll
        for (int nt = 0; nt < 8; ++nt)
#pragma unroll
            for (int i = 0; i < 4; ++i) c[mt][nt][i] = 0.f;

    // ---- Phase 1: S = Q K^T, 3-stage cp.async pipeline ----------------------
    issue1(0); CP_COMMIT();
    issue1(1); CP_COMMIT();

#pragma unroll 1
    for (int cc = 0; cc < 16; ++cc) {
        CP_WAIT(1);
        __syncthreads();
        if (cc < 14) issue1(cc + 2);
        CP_COMMIT();

        const float* Qs = smf + (cc % 3) * S1SZ;
        const float* Ks = Qs + 64 * QST;
#pragma unroll
        for (int ks = 0; ks < 16; ks += 8) {
            unsigned a[2][4];
#pragma unroll
            for (int mt = 0; mt < 2; ++mt) {
                const float* p = Qs + (wm * 32 + mt * 16 + g) * QST + ks + tg;
                a[mt][0] = f2tf(p[0]);
                a[mt][2] = f2tf(p[4]);
                a[mt][1] = f2tf(p[8 * QST]);
                a[mt][3] = f2tf(p[8 * QST + 4]);
            }
#pragma unroll
            for (int nt = 0; nt < 8; ++nt) {
                const float* p = Ks + (wn * 64 + nt * 8 + g) * KST + ks + tg;
                unsigned b0 = f2tf(p[0]);
                unsigned b1 = f2tf(p[4]);
                mma8(c[0][nt], a[0][0], a[0][1], a[0][2], a[0][3], b0, b1);
                mma8(c[1][nt], a[1][0], a[1][1], a[1][2], a[1][3], b0, b1);
            }
        }
    }
    __syncthreads();      // stage buffers dead; P/V regions now writable

    // overlap V stage 0 fetch with softmax
    issue2(0); CP_COMMIT();

    // ---- Softmax (qk_bias is softmax-invariant along keys -> skipped) -------
    const float scale = 0.0625f;  // 1/sqrt(256)
#pragma unroll
    for (int mt = 0; mt < 2; ++mt)
#pragma unroll
        for (int h = 0; h < 2; ++h) {
            float m = -1e30f;
#pragma unroll
            for (int nt = 0; nt < 8; ++nt) {
                c[mt][nt][h * 2]     *= scale;
                c[mt][nt][h * 2 + 1] *= scale;
                m = fmaxf(m, fmaxf(c[mt][nt][h * 2], c[mt][nt][h * 2 + 1]));
            }
            m = fmaxf(m, __shfl_xor_sync(0xffffffffu, m, 1));
            m = fmaxf(m, __shfl_xor_sync(0xffffffffu, m, 2));
            int row = wm * 32 + mt * 16 + h * 8 + g;
            if (tg == 0) redA[row * 4 + wn] = m;
        }
    __syncthreads();

#pragma unroll
    for (int mt = 0; mt < 2; ++mt)
#pragma unroll
        for (int h = 0; h < 2; ++h) {
            int row = wm * 32 + mt * 16 + h * 8 + g;
            float m = fmaxf(fmaxf(redA[row * 4 + 0], redA[row * 4 + 1]),
                            fmaxf(redA[row * 4 + 2], redA[row * 4 + 3]));
            float s = 0.f;
#pragma unroll
            for (int nt = 0; nt < 8; ++nt) {
                float e0 = __expf(c[mt][nt][h * 2]     - m);
                float e1 = __expf(c[mt][nt][h * 2 + 1] - m);
                c[mt][nt][h * 2]     = e0;
                c[mt][nt][h * 2 + 1] = e1;
                s += e0 + e1;
            }
            s += __shfl_xor_sync(0xffffffffu, s, 1);
            s += __shfl_xor_sync(0xffffffffu, s, 2);
            if (tg == 0) redB[row * 4 + wn] = s;
        }
    __syncthreads();

    float rinv[2][2];
#pragma unroll
    for (int mt = 0; mt < 2; ++mt)
#pragma unroll
        for (int h = 0; h < 2; ++h) {
            int row = wm * 32 + mt * 16 + h * 8 + g;
            float s = redB[row * 4 + 0] + redB[row * 4 + 1] +
                      redB[row * 4 + 2] + redB[row * 4 + 3];
            rinv[mt][h] = 1.0f / (0.9f * s);  // folds 1/(1-p) dropout rescale
        }

    // ---- Dropout + store P (tf32) to smem -----------------------------------
    const float* DU = du + (size_t)b * SDIM * SDIM;
#pragma unroll
    for (int mt = 0; mt < 2; ++mt)
#pragma unroll
        for (int h = 0; h < 2; ++h) {
            int row = wm * 32 + mt * 16 + h * 8 + g;
#pragma unroll
            for (int nt = 0; nt < 8; ++nt) {
                int col = wn * 64 + nt * 8 + tg * 2;
                float2 u = *(const float2*)&DU[(size_t)(q0 + row) * SDIM + col];
                float p0 = (u.x >= 0.1f) ? c[mt][nt][h * 2]     * rinv[mt][h] : 0.f;
                float p1 = (u.y >= 0.1f) ? c[mt][nt][h * 2 + 1] * rinv[mt][h] : 0.f;
                uint2 pv; pv.x = f2tf(p0); pv.y = f2tf(p1);
                *(uint2*)&Ps[row * PST + col] = pv;
            }
        }
    __syncthreads();

    // ---- Phase 2: O = P @ V, 2-stage cp.async pipeline -----------------------
#pragma unroll
    for (int mt = 0; mt < 2; ++mt)
#pragma unroll
        for (int nt = 0; nt < 8; ++nt)
#pragma unroll
            for (int i = 0; i < 4; ++i) c[mt][nt][i] = 0.f;

#pragma unroll 1
    for (int cc = 0; cc < 16; ++cc) {
        CP_WAIT(0);
        __syncthreads();
        if (cc < 15) issue2(cc + 1);
        CP_COMMIT();

        const unsigned* Vs = smu + V_OFF + (cc % 2) * VSTG;
        const int kbase = cc * 16;
#pragma unroll
        for (int ks = 0; ks < 16; ks += 8) {
            unsigned a[2][4];
#pragma unroll
            for (int mt = 0; mt < 2; ++mt) {
                const unsigned* p = Ps + (wm * 32 + mt * 16 + g) * PST + kbase + ks + tg;
                a[mt][0] = p[0];
                a[mt][2] = p[4];
                a[mt][1] = p[8 * PST];
                a[mt][3] = p[8 * PST + 4];
            }
#pragma unroll
            for (int nt = 0; nt < 8; ++nt) {
                const unsigned* p = Vs + (ks + tg) * VST + wn * 64 + nt * 8 + g;
                unsigned b0 = p[0];
                unsigned b1 = p[4 * VST];
                mma8(c[0][nt], a[0][0], a[0][1], a[0][2], a[0][3], b0, b1);
                mma8(c[1][nt], a[1][0], a[1][1], a[1][2], a[1][3], b0, b1);
            }
        }
    }
    __syncthreads();   // P region dead; safe to overwrite with Os

    // ---- Epilogue: stage O transposed [d][q], coalesced store ---------------
#pragma unroll
    for (int mt = 0; mt < 2; ++mt)
#pragma unroll
        for (int h = 0; h < 2; ++h) {
            int row = wm * 32 + mt * 16 + h * 8 + g;
#pragma unroll
            for (int nt = 0; nt < 8; ++nt) {
                int col = wn * 64 + nt * 8 + tg * 2;
                Os[col * OST + row]       = c[mt][nt][h * 2];
                Os[(col + 1) * OST + row] = c[mt][nt][h * 2 + 1];
            }
        }
    __syncthreads();

    float* Ob = out + (size_t)b * SDIM * SDIM;
#pragma unroll
    for (int j = 0; j < 16; ++j) {
        int idx = tid + j * 256;
        int d = idx >> 4, qv = (idx & 15) << 2;
        *(float4*)&Ob[(size_t)d * SDIM + q0 + qv] = *(float4*)&Os[d * OST + qv];
    }
}

// ---------------------------------------------------------------------------
extern "C" void kernel_launch(void* const* d_in, const int* in_sizes, int n_in,
                              void* d_out, int out_size)
{
    const float* query = (const float*)d_in[0];
    const float* key   = (const float*)d_in[1];
    const float* value = (const float*)d_in[2];
    const float* dropu = (const float*)d_in[3];
    // d_in[4] = qk_bias: constant along softmax axis -> provably dead, skipped
    const float* vw    = (const float*)d_in[5];
    const float* vb    = (const float*)d_in[6];
    float* out = (float*)d_out;

    size_t shm_a = (size_t)SMEM_WORDS * sizeof(float);      // 102400
    size_t shm_v = (size_t)(3 * VP_STG) * sizeof(float);    // 66048
    cudaFuncSetAttribute(attn_kernel,
                         cudaFuncAttributeMaxDynamicSharedMemorySize, (int)shm_a);
    cudaFuncSetAttribute(vproj_kernel,
                         cudaFuncAttributeMaxDynamicSharedMemorySize, (int)shm_v);

    dim3 grid(4, SDIM);
    vproj_kernel<<<grid, 256, shm_v>>>(value, vw, vb);
    attn_kernel<<<grid, 256, shm_a>>>(query, key, dropu, out);
}